// round 1
// baseline (speedup 1.0000x reference)
#include <cuda_runtime.h>
#include <stdint.h>

#define BB 128
#define TT 1024
#define DD 256
#define UU 48

// Scratch (allocation-free rule: __device__ globals)
__device__ float         g_logits[(size_t)BB * TT * UU];     // 25.2 MB
__device__ unsigned char g_bp[(size_t)(TT - 1) * BB * UU];   // 6.29 MB
__device__ int           g_last[BB];
__device__ unsigned char g_tags[(size_t)TT * BB];

// ---------------------------------------------------------------------------
// Kernel 1: logits = x @ kernel + bias   (131072 x 48 x 256, fp32)
// Tile: 64 rows x 48 cols per block, 128 threads, each thread 4 rows x 6 cols.
// x tile stored k-major (transposed) in smem, padded to 66 to kill conflicts.
// Accumulation: pure sequential k = 0..255 per output (deterministic order).
// ---------------------------------------------------------------------------
#define GR 64
#define GK 64

__global__ __launch_bounds__(128) void gemm_kernel(const float* __restrict__ x,
                                                   const float* __restrict__ w,
                                                   const float* __restrict__ bias) {
    __shared__ float xs[GK][66];   // [k][row], pad 66
    __shared__ float ws[GK][UU];   // [k][col]

    const int tid = threadIdx.x;
    const int tc  = tid & 7;    // col group: cols tc*6 .. tc*6+5
    const int tr  = tid >> 3;   // row group: rows tr*4 .. tr*4+3
    const size_t row0 = (size_t)blockIdx.x * GR;

    float acc[4][6];
#pragma unroll
    for (int i = 0; i < 4; i++)
#pragma unroll
        for (int j = 0; j < 6; j++) acc[i][j] = 0.0f;

    for (int kc = 0; kc < DD; kc += GK) {
        // load w chunk: GK*UU = 3072 floats = 768 uint4
        const float4* wg = (const float4*)(w + (size_t)kc * UU);
        float4* wsv = (float4*)&ws[0][0];
#pragma unroll
        for (int i = 0; i < 6; i++) wsv[tid + i * 128] = wg[tid + i * 128];

        // load x chunk transposed: 64 rows x 64 k = 1024 uint4
#pragma unroll
        for (int i = 0; i < 8; i++) {
            int j  = tid + i * 128;
            int r  = j >> 4;
            int k4 = j & 15;
            float4 f = *(const float4*)(x + (row0 + (size_t)r) * DD + kc + k4 * 4);
            xs[k4 * 4 + 0][r] = f.x;
            xs[k4 * 4 + 1][r] = f.y;
            xs[k4 * 4 + 2][r] = f.z;
            xs[k4 * 4 + 3][r] = f.w;
        }
        __syncthreads();

#pragma unroll 8
        for (int k = 0; k < GK; k++) {
            float xv[4], wv[6];
#pragma unroll
            for (int i = 0; i < 4; i++) xv[i] = xs[k][tr * 4 + i];
#pragma unroll
            for (int j = 0; j < 6; j++) wv[j] = ws[k][tc * 6 + j];
#pragma unroll
            for (int i = 0; i < 4; i++)
#pragma unroll
                for (int j = 0; j < 6; j++) acc[i][j] += xv[i] * wv[j];
        }
        __syncthreads();
    }

    float bv[6];
#pragma unroll
    for (int j = 0; j < 6; j++) bv[j] = bias[tc * 6 + j];

#pragma unroll
    for (int i = 0; i < 4; i++) {
        size_t r = row0 + tr * 4 + i;
        float* o = g_logits + r * UU + tc * 6;
#pragma unroll
        for (int j = 0; j < 6; j++) o[j] = acc[i][j] + bv[j];
    }
}

// ---------------------------------------------------------------------------
// argmax over 48 values, first-index tie-break (matches jnp.argmax):
// strict-greater replacement, left operand always holds smaller indices.
// ---------------------------------------------------------------------------
__device__ __forceinline__ void argmax48(const float (&v)[UU], float& bvo, int& bio) {
    float va[24];
    int   ia[24];
#pragma unroll
    for (int i = 0; i < 24; i++) {
        bool g = v[2 * i + 1] > v[2 * i];
        va[i] = g ? v[2 * i + 1] : v[2 * i];
        ia[i] = g ? (2 * i + 1) : (2 * i);
    }
#pragma unroll
    for (int i = 0; i < 12; i++) {
        bool g = va[2 * i + 1] > va[2 * i];
        va[i] = g ? va[2 * i + 1] : va[2 * i];
        ia[i] = g ? ia[2 * i + 1] : ia[2 * i];
    }
#pragma unroll
    for (int i = 0; i < 6; i++) {
        bool g = va[2 * i + 1] > va[2 * i];
        va[i] = g ? va[2 * i + 1] : va[2 * i];
        ia[i] = g ? ia[2 * i + 1] : ia[2 * i];
    }
#pragma unroll
    for (int i = 0; i < 3; i++) {
        bool g = va[2 * i + 1] > va[2 * i];
        va[i] = g ? va[2 * i + 1] : va[2 * i];
        ia[i] = g ? ia[2 * i + 1] : ia[2 * i];
    }
    bool g  = va[1] > va[0];
    float m = g ? va[1] : va[0];
    int  mi = g ? ia[1] : ia[0];
    bool g2 = va[2] > m;
    bvo = g2 ? va[2] : m;
    bio = g2 ? ia[2] : mi;
}

// ---------------------------------------------------------------------------
// Kernel 2: Viterbi forward. One block per batch, 64 threads (48 active).
// Thread u' holds trans column u' in registers; state double-buffered in smem.
// Logits prefetched 3 steps ahead (L2-resident after GEMM).
// ---------------------------------------------------------------------------
__global__ __launch_bounds__(64) void viterbi_fwd(const float* __restrict__ trans) {
    const int b   = blockIdx.x;
    const int tid = threadIdx.x;
    const bool act = tid < UU;
    const int u   = act ? tid : (UU - 1);

    __shared__ float st[2][UU];

    float tr[UU];
#pragma unroll
    for (int i = 0; i < UU; i++) tr[i] = trans[i * UU + u];

    const float* lg = g_logits + (size_t)b * TT * UU + u;
    if (act) st[0][tid] = lg[0];

    float f0 = lg[(size_t)1 * UU];
    float f1 = lg[(size_t)2 * UU];
    float f2 = lg[(size_t)3 * UU];
    __syncthreads();

    int p = 0;
    unsigned char* bpb = g_bp + (size_t)b * UU + u;

    for (int t = 1; t < TT; ++t) {
        float cur = f0;
        f0 = f1;
        f1 = f2;
        int tn = t + 3;
        if (tn > TT - 1) tn = TT - 1;
        f2 = lg[(size_t)tn * UU];

        float v[UU];
#pragma unroll
        for (int i = 0; i < UU; i++) v[i] = st[p][i] + tr[i];

        float bv;
        int bi;
        argmax48(v, bv, bi);

        if (act) {
            st[p ^ 1][tid] = cur + bv;
            bpb[(size_t)(t - 1) * BB * UU] = (unsigned char)bi;
        }
        __syncthreads();
        p ^= 1;
    }

    // final argmax over state -> last tag
    float v[UU];
#pragma unroll
    for (int i = 0; i < UU; i++) v[i] = st[p][i];
    float bv;
    int bi;
    argmax48(v, bv, bi);
    if (tid == 0) g_last[b] = bi;
}

// ---------------------------------------------------------------------------
// Kernel 3: backtrack. 1 block, 128 threads, thread = batch.
// bp rows (48B, tag-independent addresses) prefetched into a depth-8 register
// ring; the dependent chain is a pure-ALU 12-way SEL tree + byte extract.
// ---------------------------------------------------------------------------
__device__ __forceinline__ int sel12(const uint4 (&r)[3], int tag) {
    unsigned q0 = r[0].x, q1 = r[0].y, q2 = r[0].z, q3 = r[0].w;
    unsigned q4 = r[1].x, q5 = r[1].y, q6 = r[1].z, q7 = r[1].w;
    unsigned q8 = r[2].x, q9 = r[2].y, q10 = r[2].z, q11 = r[2].w;
    int t2 = tag >> 2;
    unsigned w =
        t2 < 6 ? (t2 < 3 ? (t2 < 1 ? q0 : (t2 < 2 ? q1 : q2))
                         : (t2 < 4 ? q3 : (t2 < 5 ? q4 : q5)))
               : (t2 < 9 ? (t2 < 7 ? q6 : (t2 < 8 ? q7 : q8))
                         : (t2 < 10 ? q9 : (t2 < 11 ? q10 : q11)));
    return (int)((w >> ((tag & 3) << 3)) & 0xFFu);
}

__global__ __launch_bounds__(128) void backtrack_kernel() {
    const int b = threadIdx.x;
    int tag = g_last[b];
    g_tags[(size_t)(TT - 1) * BB + b] = (unsigned char)tag;

    uint4 ring[8][3];

    // prologue: fill slots for steps 1022..1015 (slot = s & 7)
#pragma unroll
    for (int d = 0; d < 8; ++d) {
        int s = (TT - 2) - d;  // 1022..1015
        const uint4* r = (const uint4*)(g_bp + (size_t)s * BB * UU + (size_t)b * UU);
        ring[s & 7][0] = r[0];
        ring[s & 7][1] = r[1];
        ring[s & 7][2] = r[2];
    }

    // main: steps 1022..7 in 127 groups of 8
    for (int g = 0; g < 127; ++g) {
        int base = (TT - 2) - g * 8;
#pragma unroll
        for (int d = 0; d < 8; ++d) {
            int s = base - d;
            const int slot = (6 - d) & 7;   // == s & 7, compile-time
            tag = sel12(ring[slot], tag);
            g_tags[(size_t)s * BB + b] = (unsigned char)tag;
            int sp = s - 8;
            if (sp >= 0) {
                const uint4* r = (const uint4*)(g_bp + (size_t)sp * BB * UU + (size_t)b * UU);
                ring[slot][0] = r[0];
                ring[slot][1] = r[1];
                ring[slot][2] = r[2];
            }
        }
    }

    // epilogue: steps 6..0 (already prefetched)
#pragma unroll
    for (int d = 0; d < 7; ++d) {
        int s = 6 - d;
        tag = sel12(ring[s & 7], tag);
        g_tags[(size_t)s * BB + b] = (unsigned char)tag;
    }
}

// ---------------------------------------------------------------------------
// Kernel 4: emit (transpose [t][b] bytes -> [b][t] float32)
// ---------------------------------------------------------------------------
__global__ __launch_bounds__(256) void emit_kernel(float* __restrict__ out) {
    int idx = blockIdx.x * blockDim.x + threadIdx.x;
    int b = idx >> 10;
    int t = idx & (TT - 1);
    out[idx] = (float)g_tags[(size_t)t * BB + b];
}

// ---------------------------------------------------------------------------
extern "C" void kernel_launch(void* const* d_in, const int* in_sizes, int n_in,
                              void* d_out, int out_size) {
    const float* x     = (const float*)d_in[0];  // (128,1024,256)
    const float* kern  = (const float*)d_in[1];  // (256,48)
    const float* bias  = (const float*)d_in[2];  // (48,)
    const float* chain = (const float*)d_in[3];  // (48,48)
    float* out = (float*)d_out;                  // (128,1024) float32

    gemm_kernel<<<(BB * TT) / GR, 128>>>(x, kern, bias);
    viterbi_fwd<<<BB, 64>>>(chain);
    backtrack_kernel<<<1, 128>>>();
    emit_kernel<<<(BB * TT) / 256, 256>>>(out);
}

// round 2
// speedup vs baseline: 1.2890x; 1.2890x over previous
#include <cuda_runtime.h>
#include <stdint.h>

#define BB 128
#define TT 1024
#define DD 256
#define UU 48

// Scratch (allocation-free rule: __device__ globals)
__device__ float         g_logits[(size_t)BB * TT * UU];     // 25.2 MB
__device__ unsigned char g_bp[(size_t)(TT - 1) * BB * UU];   // 6.29 MB
__device__ int           g_last[BB];
__device__ unsigned char g_tags[(size_t)TT * BB];

#define ADD_F32X2(out, a, b) \
    asm("add.rn.f32x2 %0, %1, %2;" : "=l"(out) : "l"(a), "l"(b))

// ---------------------------------------------------------------------------
// Kernel 1: logits = x @ kernel + bias   (131072 x 48 x 256, fp32)
// 128 rows x 48 cols per block, 128 threads, thread tile 4 rows x 12 cols.
// Inner loop: 1 LDS.64x2 + 3 LDS.128 + 48 FFMA per k (issue ~= FMA pipe floor).
// Accumulation: sequential k = 0..255 (deterministic, matches R1 rel_err=0).
// ---------------------------------------------------------------------------
#define GR 128
#define GK 64
#define XPAD 130   // row-dim pad: stride 130 floats keeps STS conflicts <= 4-way

__global__ __launch_bounds__(128) void gemm_kernel(const float* __restrict__ x,
                                                   const float* __restrict__ w,
                                                   const float* __restrict__ bias) {
    __shared__ float xs[GK][XPAD];  // [k][row]
    __shared__ float ws[GK][UU];    // [k][col]

    const int tid = threadIdx.x;
    const int tc  = tid & 3;    // col group: cols tc*12 .. +11
    const int tr  = tid >> 2;   // row group: rows tr*4 .. +3 (tr 0..31)
    const size_t row0 = (size_t)blockIdx.x * GR;

    float acc[4][12];
#pragma unroll
    for (int i = 0; i < 4; i++)
#pragma unroll
        for (int j = 0; j < 12; j++) acc[i][j] = 0.0f;

    for (int kc = 0; kc < DD; kc += GK) {
        // w chunk: GK*UU = 3072 floats = 768 float4
        const float4* wg = (const float4*)(w + (size_t)kc * UU);
        float4* wsv = (float4*)&ws[0][0];
#pragma unroll
        for (int i = 0; i < 6; i++) wsv[tid + i * 128] = wg[tid + i * 128];

        // x chunk transposed: 128 rows x 64 k = 2048 float4
#pragma unroll
        for (int i = 0; i < 16; i++) {
            int j  = tid + i * 128;
            int r  = j >> 4;      // 16 float4 per row
            int k4 = j & 15;
            float4 f = *(const float4*)(x + (row0 + (size_t)r) * DD + kc + k4 * 4);
            xs[k4 * 4 + 0][r] = f.x;
            xs[k4 * 4 + 1][r] = f.y;
            xs[k4 * 4 + 2][r] = f.z;
            xs[k4 * 4 + 3][r] = f.w;
        }
        __syncthreads();

#pragma unroll 4
        for (int k = 0; k < GK; k++) {
            float xv[4], wv[12];
            // rows: 2 x LDS.64 (8B aligned for any k with pad 130)
            float2 xa = *(const float2*)&xs[k][tr * 4];
            float2 xb = *(const float2*)&xs[k][tr * 4 + 2];
            xv[0] = xa.x; xv[1] = xa.y; xv[2] = xb.x; xv[3] = xb.y;
            // cols: 3 x LDS.128 (tc*12 floats = 48B aligned)
#pragma unroll
            for (int q = 0; q < 3; q++) {
                float4 wq = *(const float4*)&ws[k][tc * 12 + q * 4];
                wv[q * 4 + 0] = wq.x; wv[q * 4 + 1] = wq.y;
                wv[q * 4 + 2] = wq.z; wv[q * 4 + 3] = wq.w;
            }
#pragma unroll
            for (int i = 0; i < 4; i++)
#pragma unroll
                for (int j = 0; j < 12; j++) acc[i][j] += xv[i] * wv[j];
        }
        __syncthreads();
    }

    float bv[12];
#pragma unroll
    for (int j = 0; j < 12; j++) bv[j] = bias[tc * 12 + j];

#pragma unroll
    for (int i = 0; i < 4; i++) {
        size_t r = row0 + tr * 4 + i;
        float* o = g_logits + r * UU + tc * 12;
#pragma unroll
        for (int j = 0; j < 12; j++) o[j] = acc[i][j] + bv[j];
    }
}

// ---------------------------------------------------------------------------
// Exact (val, argmax-first-index) over 24 candidates held as 12 packed f32x2.
// Left operand of every node covers strictly smaller indices; replacement is
// strict-greater => first-index tie-break, matching jnp.argmax.
// ---------------------------------------------------------------------------
__device__ __forceinline__ void argmax24(const unsigned long long (&c)[12],
                                         float& bvo, int& bio) {
    float v[12];
    int   ix[12];
#pragma unroll
    for (int j = 0; j < 12; j++) {
        float lo = __uint_as_float((unsigned)(c[j] & 0xFFFFFFFFull));
        float hi = __uint_as_float((unsigned)(c[j] >> 32));
        bool g = hi > lo;
        v[j]  = g ? hi : lo;
        ix[j] = 2 * j + (g ? 1 : 0);
    }
#pragma unroll
    for (int j = 0; j < 6; j++) {
        bool g = v[2 * j + 1] > v[2 * j];
        v[j]  = g ? v[2 * j + 1] : v[2 * j];
        ix[j] = g ? ix[2 * j + 1] : ix[2 * j];
    }
#pragma unroll
    for (int j = 0; j < 3; j++) {
        bool g = v[2 * j + 1] > v[2 * j];
        v[j]  = g ? v[2 * j + 1] : v[2 * j];
        ix[j] = g ? ix[2 * j + 1] : ix[2 * j];
    }
    bool g  = v[1] > v[0];
    float m = g ? v[1] : v[0];
    int  mi = g ? ix[1] : ix[0];
    bool g2 = v[2] > m;
    bvo = g2 ? v[2] : m;
    bio = g2 ? ix[2] : mi;
}

// ---------------------------------------------------------------------------
// Kernel 2: Viterbi forward. One block per batch, 96 threads (3 warps).
// Thread (u = tid>>1, h = tid&1) reduces candidates i in [24h, 24h+24) for
// output u; adjacent lanes combine via shfl.down 1 (odd half = larger idx,
// taken only on strict-greater). Adds are packed add.rn.f32x2 on ulonglong2
// state reads. trans column pre-packed into 12 x u64 registers.
// ---------------------------------------------------------------------------
__global__ __launch_bounds__(96) void viterbi_fwd(const float* __restrict__ trans) {
    const int b   = blockIdx.x;
    const int tid = threadIdx.x;
    const int u   = tid >> 1;
    const int h   = tid & 1;
    const int base = 24 * h;

    __shared__ __align__(16) float st[2][UU];

    // pack trans[i][u], i in [base, base+24) into 12 f32x2 regs
    unsigned long long tr2[12];
#pragma unroll
    for (int j = 0; j < 12; j++) {
        unsigned lo = __float_as_uint(trans[(base + 2 * j) * UU + u]);
        unsigned hi = __float_as_uint(trans[(base + 2 * j + 1) * UU + u]);
        tr2[j] = (unsigned long long)lo | ((unsigned long long)hi << 32);
    }

    const float* lg = g_logits + (size_t)b * TT * UU + u;
    if (h == 0) st[0][u] = lg[0];

    float f0 = lg[(size_t)1 * UU];
    float f1 = lg[(size_t)2 * UU];
    float f2 = lg[(size_t)3 * UU];
    __syncthreads();

    int p = 0;
    unsigned char* bpb = g_bp + (size_t)b * UU + u;

    for (int t = 1; t < TT; ++t) {
        float cur = f0;
        f0 = f1;
        f1 = f2;
        int tn = t + 3;
        if (tn > TT - 1) tn = TT - 1;
        f2 = lg[(size_t)tn * UU];

        // 24 candidates: 6 x LDS.128, 12 x packed add
        unsigned long long c[12];
#pragma unroll
        for (int m = 0; m < 6; m++) {
            ulonglong2 s = *(const ulonglong2*)&st[p][base + 4 * m];
            ADD_F32X2(c[2 * m + 0], s.x, tr2[2 * m + 0]);
            ADD_F32X2(c[2 * m + 1], s.y, tr2[2 * m + 1]);
        }

        float bv;
        int bi;
        argmax24(c, bv, bi);
        bi += base;  // global candidate index

        // combine halves: even lane (idx 0..23) takes odd lane (24..47)
        // only on strict greater -> first-index tie-break preserved
        float ov = __shfl_down_sync(0xFFFFFFFFu, bv, 1);
        int   oi = __shfl_down_sync(0xFFFFFFFFu, bi, 1);
        bool g = ov > bv;
        float mv = g ? ov : bv;
        int   mi = g ? oi : bi;

        if (h == 0) {
            st[p ^ 1][u] = cur + mv;
            bpb[(size_t)(t - 1) * BB * UU] = (unsigned char)mi;
        }
        __syncthreads();
        p ^= 1;
    }

    if (tid == 0) {
        float bv = st[p][0];
        int bi = 0;
#pragma unroll
        for (int i = 1; i < UU; i++) {
            if (st[p][i] > bv) { bv = st[p][i]; bi = i; }
        }
        g_last[b] = bi;
    }
}

// ---------------------------------------------------------------------------
// Kernel 3: backtrack. 1 block, 128 threads, thread = batch.
// bp rows (48B, tag-independent addresses) prefetched into a depth-8 register
// ring; the dependent chain is a pure-ALU 12-way SEL tree + byte extract.
// ---------------------------------------------------------------------------
__device__ __forceinline__ int sel12(const uint4 (&r)[3], int tag) {
    unsigned q0 = r[0].x, q1 = r[0].y, q2 = r[0].z, q3 = r[0].w;
    unsigned q4 = r[1].x, q5 = r[1].y, q6 = r[1].z, q7 = r[1].w;
    unsigned q8 = r[2].x, q9 = r[2].y, q10 = r[2].z, q11 = r[2].w;
    int t2 = tag >> 2;
    unsigned w =
        t2 < 6 ? (t2 < 3 ? (t2 < 1 ? q0 : (t2 < 2 ? q1 : q2))
                         : (t2 < 4 ? q3 : (t2 < 5 ? q4 : q5)))
               : (t2 < 9 ? (t2 < 7 ? q6 : (t2 < 8 ? q7 : q8))
                         : (t2 < 10 ? q9 : (t2 < 11 ? q10 : q11)));
    return (int)((w >> ((tag & 3) << 3)) & 0xFFu);
}

__global__ __launch_bounds__(128) void backtrack_kernel() {
    const int b = threadIdx.x;
    int tag = g_last[b];
    g_tags[(size_t)(TT - 1) * BB + b] = (unsigned char)tag;

    uint4 ring[8][3];

#pragma unroll
    for (int d = 0; d < 8; ++d) {
        int s = (TT - 2) - d;  // 1022..1015
        const uint4* r = (const uint4*)(g_bp + (size_t)s * BB * UU + (size_t)b * UU);
        ring[s & 7][0] = r[0];
        ring[s & 7][1] = r[1];
        ring[s & 7][2] = r[2];
    }

    for (int g = 0; g < 127; ++g) {
        int base = (TT - 2) - g * 8;
#pragma unroll
        for (int d = 0; d < 8; ++d) {
            int s = base - d;
            const int slot = (6 - d) & 7;   // == s & 7, compile-time
            tag = sel12(ring[slot], tag);
            g_tags[(size_t)s * BB + b] = (unsigned char)tag;
            int sp = s - 8;
            if (sp >= 0) {
                const uint4* r = (const uint4*)(g_bp + (size_t)sp * BB * UU + (size_t)b * UU);
                ring[slot][0] = r[0];
                ring[slot][1] = r[1];
                ring[slot][2] = r[2];
            }
        }
    }

#pragma unroll
    for (int d = 0; d < 7; ++d) {
        int s = 6 - d;
        tag = sel12(ring[s & 7], tag);
        g_tags[(size_t)s * BB + b] = (unsigned char)tag;
    }
}

// ---------------------------------------------------------------------------
// Kernel 4: emit (transpose [t][b] bytes -> [b][t] float32)
// ---------------------------------------------------------------------------
__global__ __launch_bounds__(256) void emit_kernel(float* __restrict__ out) {
    int idx = blockIdx.x * blockDim.x + threadIdx.x;
    int b = idx >> 10;
    int t = idx & (TT - 1);
    out[idx] = (float)g_tags[(size_t)t * BB + b];
}

// ---------------------------------------------------------------------------
extern "C" void kernel_launch(void* const* d_in, const int* in_sizes, int n_in,
                              void* d_out, int out_size) {
    const float* x     = (const float*)d_in[0];  // (128,1024,256)
    const float* kern  = (const float*)d_in[1];  // (256,48)
    const float* bias  = (const float*)d_in[2];  // (48,)
    const float* chain = (const float*)d_in[3];  // (48,48)
    float* out = (float*)d_out;                  // (128,1024) float32

    gemm_kernel<<<(BB * TT) / GR, 128>>>(x, kern, bias);
    viterbi_fwd<<<BB, 96>>>(chain);
    backtrack_kernel<<<1, 128>>>();
    emit_kernel<<<(BB * TT) / 256, 256>>>(out);
}

// round 3
// speedup vs baseline: 1.3696x; 1.0625x over previous
#include <cuda_runtime.h>
#include <stdint.h>

#define BB 128
#define TT 1024
#define DD 256
#define UU 48

// Scratch (allocation-free rule: __device__ globals)
__device__ float         g_logits[(size_t)BB * TT * UU];     // 25.2 MB
__device__ unsigned char g_bp[(size_t)(TT - 1) * BB * UU];   // 6.29 MB
__device__ int           g_last[BB];

#define ADD_F32X2(out, a, b) \
    asm("add.rn.f32x2 %0, %1, %2;" : "=l"(out) : "l"(a), "l"(b))

// ---------------------------------------------------------------------------
// Kernel 1: logits = x @ kernel + bias   (131072 x 48 x 256, fp32)
// 128 rows x 48 cols per block, 128 threads, thread tile 4 rows x 12 cols.
// Accumulation: sequential k = 0..255 (deterministic, rel_err = 0 so far).
// ---------------------------------------------------------------------------
#define GR 128
#define GK 64
#define XPAD 130

__global__ __launch_bounds__(128) void gemm_kernel(const float* __restrict__ x,
                                                   const float* __restrict__ w,
                                                   const float* __restrict__ bias) {
    __shared__ float xs[GK][XPAD];  // [k][row]
    __shared__ float ws[GK][UU];    // [k][col]

    const int tid = threadIdx.x;
    const int tc  = tid & 3;    // cols tc*12 .. +11
    const int tr  = tid >> 2;   // rows tr*4 .. +3
    const size_t row0 = (size_t)blockIdx.x * GR;

    float acc[4][12];
#pragma unroll
    for (int i = 0; i < 4; i++)
#pragma unroll
        for (int j = 0; j < 12; j++) acc[i][j] = 0.0f;

    for (int kc = 0; kc < DD; kc += GK) {
        const float4* wg = (const float4*)(w + (size_t)kc * UU);
        float4* wsv = (float4*)&ws[0][0];
#pragma unroll
        for (int i = 0; i < 6; i++) wsv[tid + i * 128] = wg[tid + i * 128];

#pragma unroll
        for (int i = 0; i < 16; i++) {
            int j  = tid + i * 128;
            int r  = j >> 4;
            int k4 = j & 15;
            float4 f = *(const float4*)(x + (row0 + (size_t)r) * DD + kc + k4 * 4);
            xs[k4 * 4 + 0][r] = f.x;
            xs[k4 * 4 + 1][r] = f.y;
            xs[k4 * 4 + 2][r] = f.z;
            xs[k4 * 4 + 3][r] = f.w;
        }
        __syncthreads();

#pragma unroll 4
        for (int k = 0; k < GK; k++) {
            float xv[4], wv[12];
            float2 xa = *(const float2*)&xs[k][tr * 4];
            float2 xb = *(const float2*)&xs[k][tr * 4 + 2];
            xv[0] = xa.x; xv[1] = xa.y; xv[2] = xb.x; xv[3] = xb.y;
#pragma unroll
            for (int q = 0; q < 3; q++) {
                float4 wq = *(const float4*)&ws[k][tc * 12 + q * 4];
                wv[q * 4 + 0] = wq.x; wv[q * 4 + 1] = wq.y;
                wv[q * 4 + 2] = wq.z; wv[q * 4 + 3] = wq.w;
            }
#pragma unroll
            for (int i = 0; i < 4; i++)
#pragma unroll
                for (int j = 0; j < 12; j++) acc[i][j] += xv[i] * wv[j];
        }
        __syncthreads();
    }

    float bv[12];
#pragma unroll
    for (int j = 0; j < 12; j++) bv[j] = bias[tc * 12 + j];

#pragma unroll
    for (int i = 0; i < 4; i++) {
        size_t r = row0 + tr * 4 + i;
        float* o = g_logits + r * UU + tc * 12;
#pragma unroll
        for (int j = 0; j < 12; j++) o[j] = acc[i][j] + bv[j];
    }
}

// ---------------------------------------------------------------------------
// Exact (val, argmax-first-index) over 24 candidates held as 12 packed f32x2.
// Left operand of every node covers strictly smaller indices; replacement is
// strict-greater => first-index tie-break, matching jnp.argmax.
// ---------------------------------------------------------------------------
__device__ __forceinline__ void argmax24(const unsigned long long (&c)[12],
                                         float& bvo, int& bio) {
    float v[12];
    int   ix[12];
#pragma unroll
    for (int j = 0; j < 12; j++) {
        float lo = __uint_as_float((unsigned)(c[j] & 0xFFFFFFFFull));
        float hi = __uint_as_float((unsigned)(c[j] >> 32));
        bool g = hi > lo;
        v[j]  = g ? hi : lo;
        ix[j] = 2 * j + (g ? 1 : 0);
    }
#pragma unroll
    for (int j = 0; j < 6; j++) {
        bool g = v[2 * j + 1] > v[2 * j];
        v[j]  = g ? v[2 * j + 1] : v[2 * j];
        ix[j] = g ? ix[2 * j + 1] : ix[2 * j];
    }
#pragma unroll
    for (int j = 0; j < 3; j++) {
        bool g = v[2 * j + 1] > v[2 * j];
        v[j]  = g ? v[2 * j + 1] : v[2 * j];
        ix[j] = g ? ix[2 * j + 1] : ix[2 * j];
    }
    bool g  = v[1] > v[0];
    float m = g ? v[1] : v[0];
    int  mi = g ? ix[1] : ix[0];
    bool g2 = v[2] > m;
    bvo = g2 ? v[2] : m;
    bio = g2 ? ix[2] : mi;
}

// ---------------------------------------------------------------------------
// Kernel 2: Viterbi forward. One block per batch, 96 threads (3 warps).
// Thread (u = tid>>1, h = tid&1) reduces candidates i in [24h, 24h+24);
// adjacent lanes combine via shfl.down 1. Logits prefetched 4 deep.
// ---------------------------------------------------------------------------
__global__ __launch_bounds__(96) void viterbi_fwd(const float* __restrict__ trans) {
    const int b   = blockIdx.x;
    const int tid = threadIdx.x;
    const int u   = tid >> 1;
    const int h   = tid & 1;
    const int base = 24 * h;

    __shared__ __align__(16) float st[2][UU];

    unsigned long long tr2[12];
#pragma unroll
    for (int j = 0; j < 12; j++) {
        unsigned lo = __float_as_uint(trans[(base + 2 * j) * UU + u]);
        unsigned hi = __float_as_uint(trans[(base + 2 * j + 1) * UU + u]);
        tr2[j] = (unsigned long long)lo | ((unsigned long long)hi << 32);
    }

    const float* lg = g_logits + (size_t)b * TT * UU + u;
    if (h == 0) st[0][u] = lg[0];

    float f0 = lg[(size_t)1 * UU];
    float f1 = lg[(size_t)2 * UU];
    float f2 = lg[(size_t)3 * UU];
    float f3 = lg[(size_t)4 * UU];
    __syncthreads();

    int p = 0;
    unsigned char* bpb = g_bp + (size_t)b * UU + u;

    for (int t = 1; t < TT; ++t) {
        float cur = f0;
        f0 = f1;
        f1 = f2;
        f2 = f3;
        int tn = t + 4;
        if (tn > TT - 1) tn = TT - 1;
        f3 = lg[(size_t)tn * UU];

        unsigned long long c[12];
#pragma unroll
        for (int m = 0; m < 6; m++) {
            ulonglong2 s = *(const ulonglong2*)&st[p][base + 4 * m];
            ADD_F32X2(c[2 * m + 0], s.x, tr2[2 * m + 0]);
            ADD_F32X2(c[2 * m + 1], s.y, tr2[2 * m + 1]);
        }

        float bv;
        int bi;
        argmax24(c, bv, bi);
        bi += base;

        float ov = __shfl_down_sync(0xFFFFFFFFu, bv, 1);
        int   oi = __shfl_down_sync(0xFFFFFFFFu, bi, 1);
        bool g = ov > bv;
        float mv = g ? ov : bv;
        int   mi = g ? oi : bi;

        if (h == 0) {
            st[p ^ 1][u] = cur + mv;
            bpb[(size_t)(t - 1) * BB * UU] = (unsigned char)mi;
        }
        __syncthreads();
        p ^= 1;
    }

    if (tid == 0) {
        float bv = st[p][0];
        int bi = 0;
#pragma unroll
        for (int i = 1; i < UU; i++) {
            if (st[p][i] > bv) { bv = st[p][i]; bi = i; }
        }
        g_last[b] = bi;
    }
}

// ---------------------------------------------------------------------------
// Kernel 3: backtrack + emit fused. 128 blocks, one batch-chain per block
// (spreads the 6.3MB bp stream across SMs; per-SM L1tex load /128).
// bp rows prefetched into a depth-8 register ring; dependent chain is a
// pure-ALU 12-way SEL tree + byte extract. Writes float output directly.
// ---------------------------------------------------------------------------
__device__ __forceinline__ int sel12(const uint4 (&r)[3], int tag) {
    unsigned q0 = r[0].x, q1 = r[0].y, q2 = r[0].z, q3 = r[0].w;
    unsigned q4 = r[1].x, q5 = r[1].y, q6 = r[1].z, q7 = r[1].w;
    unsigned q8 = r[2].x, q9 = r[2].y, q10 = r[2].z, q11 = r[2].w;
    int t2 = tag >> 2;
    unsigned w =
        t2 < 6 ? (t2 < 3 ? (t2 < 1 ? q0 : (t2 < 2 ? q1 : q2))
                         : (t2 < 4 ? q3 : (t2 < 5 ? q4 : q5)))
               : (t2 < 9 ? (t2 < 7 ? q6 : (t2 < 8 ? q7 : q8))
                         : (t2 < 10 ? q9 : (t2 < 11 ? q10 : q11)));
    return (int)((w >> ((tag & 3) << 3)) & 0xFFu);
}

__global__ __launch_bounds__(32) void backtrack_kernel(float* __restrict__ out) {
    const int b = blockIdx.x;
    if (threadIdx.x != 0) return;

    int tag = g_last[b];
    float* ob = out + (size_t)b * TT;
    ob[TT - 1] = (float)tag;

    uint4 ring[8][3];

#pragma unroll
    for (int d = 0; d < 8; ++d) {
        int s = (TT - 2) - d;  // 1022..1015
        const uint4* r = (const uint4*)(g_bp + (size_t)s * BB * UU + (size_t)b * UU);
        ring[s & 7][0] = r[0];
        ring[s & 7][1] = r[1];
        ring[s & 7][2] = r[2];
    }

    for (int g = 0; g < 127; ++g) {
        int sbase = (TT - 2) - g * 8;
#pragma unroll
        for (int d = 0; d < 8; ++d) {
            int s = sbase - d;
            const int slot = (6 - d) & 7;   // == s & 7, compile-time
            tag = sel12(ring[slot], tag);
            ob[s] = (float)tag;
            int sp = s - 8;
            if (sp >= 0) {
                const uint4* r = (const uint4*)(g_bp + (size_t)sp * BB * UU + (size_t)b * UU);
                ring[slot][0] = r[0];
                ring[slot][1] = r[1];
                ring[slot][2] = r[2];
            }
        }
    }

#pragma unroll
    for (int d = 0; d < 7; ++d) {
        int s = 6 - d;
        tag = sel12(ring[s & 7], tag);
        ob[s] = (float)tag;
    }
}

// ---------------------------------------------------------------------------
extern "C" void kernel_launch(void* const* d_in, const int* in_sizes, int n_in,
                              void* d_out, int out_size) {
    const float* x     = (const float*)d_in[0];  // (128,1024,256)
    const float* kern  = (const float*)d_in[1];  // (256,48)
    const float* bias  = (const float*)d_in[2];  // (48,)
    const float* chain = (const float*)d_in[3];  // (48,48)
    float* out = (float*)d_out;                  // (128,1024) float32

    gemm_kernel<<<(BB * TT) / GR, 128>>>(x, kern, bias);
    viterbi_fwd<<<BB, 96>>>(chain);
    backtrack_kernel<<<BB, 1>>>(out);
}

// round 4
// speedup vs baseline: 1.4222x; 1.0385x over previous
#include <cuda_runtime.h>
#include <stdint.h>

#define BB 128
#define TT 1024
#define DD 256
#define UU 48

// Scratch (allocation-free rule: __device__ globals)
__device__ float         g_logits[(size_t)BB * TT * UU];     // 25.2 MB
__device__ unsigned char g_bp[(size_t)(TT - 1) * BB * UU];   // 6.29 MB
__device__ int           g_last[BB];

#define ADD_F32X2(out, a, b) \
    asm("add.rn.f32x2 %0, %1, %2;" : "=l"(out) : "l"(a), "l"(b))

// ---------------------------------------------------------------------------
// Kernel 1: logits = x @ kernel + bias   (131072 x 48 x 256, fp32)
// Measured 105.7us ~= 1.12x the fp32 FFMA chip floor; keep.
// ---------------------------------------------------------------------------
#define GR 128
#define GK 64
#define XPAD 130

__global__ __launch_bounds__(128) void gemm_kernel(const float* __restrict__ x,
                                                   const float* __restrict__ w,
                                                   const float* __restrict__ bias) {
    __shared__ float xs[GK][XPAD];  // [k][row]
    __shared__ float ws[GK][UU];    // [k][col]

    const int tid = threadIdx.x;
    const int tc  = tid & 3;    // cols tc*12 .. +11
    const int tr  = tid >> 2;   // rows tr*4 .. +3
    const size_t row0 = (size_t)blockIdx.x * GR;

    float acc[4][12];
#pragma unroll
    for (int i = 0; i < 4; i++)
#pragma unroll
        for (int j = 0; j < 12; j++) acc[i][j] = 0.0f;

    for (int kc = 0; kc < DD; kc += GK) {
        const float4* wg = (const float4*)(w + (size_t)kc * UU);
        float4* wsv = (float4*)&ws[0][0];
#pragma unroll
        for (int i = 0; i < 6; i++) wsv[tid + i * 128] = wg[tid + i * 128];

#pragma unroll
        for (int i = 0; i < 16; i++) {
            int j  = tid + i * 128;
            int r  = j >> 4;
            int k4 = j & 15;
            float4 f = *(const float4*)(x + (row0 + (size_t)r) * DD + kc + k4 * 4);
            xs[k4 * 4 + 0][r] = f.x;
            xs[k4 * 4 + 1][r] = f.y;
            xs[k4 * 4 + 2][r] = f.z;
            xs[k4 * 4 + 3][r] = f.w;
        }
        __syncthreads();

#pragma unroll 4
        for (int k = 0; k < GK; k++) {
            float xv[4], wv[12];
            float2 xa = *(const float2*)&xs[k][tr * 4];
            float2 xb = *(const float2*)&xs[k][tr * 4 + 2];
            xv[0] = xa.x; xv[1] = xa.y; xv[2] = xb.x; xv[3] = xb.y;
#pragma unroll
            for (int q = 0; q < 3; q++) {
                float4 wq = *(const float4*)&ws[k][tc * 12 + q * 4];
                wv[q * 4 + 0] = wq.x; wv[q * 4 + 1] = wq.y;
                wv[q * 4 + 2] = wq.z; wv[q * 4 + 3] = wq.w;
            }
#pragma unroll
            for (int i = 0; i < 4; i++)
#pragma unroll
                for (int j = 0; j < 12; j++) acc[i][j] += xv[i] * wv[j];
        }
        __syncthreads();
    }

    float bv[12];
#pragma unroll
    for (int j = 0; j < 12; j++) bv[j] = bias[tc * 12 + j];

#pragma unroll
    for (int i = 0; i < 4; i++) {
        size_t r = row0 + tr * 4 + i;
        float* o = g_logits + r * UU + tc * 12;
#pragma unroll
        for (int j = 0; j < 12; j++) o[j] = acc[i][j] + bv[j];
    }
}

// ---------------------------------------------------------------------------
// Exact (val, argmax-first-index) over 24 candidates.
// VALUE chain: pure FMNMX (fmaxf), fixed-lat 4/level -> ~24 cyc depth.
// INDEX chain: FSETP(b>a)+SEL trails the value chain; feeds only the bp
// store, not the state recurrence. Tie-break identical to jnp.argmax
// (strict-greater replacement, left operand covers smaller indices).
// ---------------------------------------------------------------------------
__device__ __forceinline__ void argmax24(const unsigned long long (&c)[12],
                                         float& bvo, int& bio) {
    float v[12];
    int   ix[12];
#pragma unroll
    for (int j = 0; j < 12; j++) {
        float lo = __uint_as_float((unsigned)(c[j] & 0xFFFFFFFFull));
        float hi = __uint_as_float((unsigned)(c[j] >> 32));
        v[j]  = fmaxf(lo, hi);
        ix[j] = (hi > lo) ? (2 * j + 1) : (2 * j);
    }
#pragma unroll
    for (int j = 0; j < 6; j++) {
        float a = v[2 * j], b = v[2 * j + 1];
        v[j]  = fmaxf(a, b);
        ix[j] = (b > a) ? ix[2 * j + 1] : ix[2 * j];
    }
#pragma unroll
    for (int j = 0; j < 3; j++) {
        float a = v[2 * j], b = v[2 * j + 1];
        v[j]  = fmaxf(a, b);
        ix[j] = (b > a) ? ix[2 * j + 1] : ix[2 * j];
    }
    float m01 = fmaxf(v[0], v[1]);
    int  i01  = (v[1] > v[0]) ? ix[1] : ix[0];
    bvo = fmaxf(m01, v[2]);
    bio = (v[2] > m01) ? ix[2] : i01;
}

// ---------------------------------------------------------------------------
// Kernel 2: Viterbi forward. One block per batch, 96 threads (3 warps).
// Thread (u = tid>>1, h = tid&1) reduces candidates i in [24h, 24h+24);
// halves combine via shfl.down 1 (value via fmaxf on chain, idx trailing).
// ---------------------------------------------------------------------------
__global__ __launch_bounds__(96) void viterbi_fwd(const float* __restrict__ trans) {
    const int b   = blockIdx.x;
    const int tid = threadIdx.x;
    const int u   = tid >> 1;
    const int h   = tid & 1;
    const int base = 24 * h;

    __shared__ __align__(16) float st[2][UU];

    unsigned long long tr2[12];
#pragma unroll
    for (int j = 0; j < 12; j++) {
        unsigned lo = __float_as_uint(trans[(base + 2 * j) * UU + u]);
        unsigned hi = __float_as_uint(trans[(base + 2 * j + 1) * UU + u]);
        tr2[j] = (unsigned long long)lo | ((unsigned long long)hi << 32);
    }

    const float* lg = g_logits + (size_t)b * TT * UU + u;
    if (h == 0) st[0][u] = lg[0];

    float f0 = lg[(size_t)1 * UU];
    float f1 = lg[(size_t)2 * UU];
    float f2 = lg[(size_t)3 * UU];
    float f3 = lg[(size_t)4 * UU];
    __syncthreads();

    int p = 0;
    unsigned char* bpb = g_bp + (size_t)b * UU + u;

    for (int t = 1; t < TT; ++t) {
        float cur = f0;
        f0 = f1;
        f1 = f2;
        f2 = f3;
        int tn = t + 4;
        if (tn > TT - 1) tn = TT - 1;
        f3 = lg[(size_t)tn * UU];

        unsigned long long c[12];
#pragma unroll
        for (int m = 0; m < 6; m++) {
            ulonglong2 s = *(const ulonglong2*)&st[p][base + 4 * m];
            ADD_F32X2(c[2 * m + 0], s.x, tr2[2 * m + 0]);
            ADD_F32X2(c[2 * m + 1], s.y, tr2[2 * m + 1]);
        }

        float bv;
        int bi;
        argmax24(c, bv, bi);
        bi += base;

        float ov = __shfl_down_sync(0xFFFFFFFFu, bv, 1);
        int   oi = __shfl_down_sync(0xFFFFFFFFu, bi, 1);
        float mv = fmaxf(bv, ov);          // state chain: FMNMX
        int   mi = (ov > bv) ? oi : bi;    // idx chain: trails, feeds STG only

        if (h == 0) {
            st[p ^ 1][u] = cur + mv;
            bpb[(size_t)(t - 1) * BB * UU] = (unsigned char)mi;
        }
        __syncthreads();
        p ^= 1;
    }

    if (tid == 0) {
        float bv = st[p][0];
        int bi = 0;
#pragma unroll
        for (int i = 1; i < UU; i++) {
            if (st[p][i] > bv) { bv = st[p][i]; bi = i; }
        }
        g_last[b] = bi;
    }
}

// ---------------------------------------------------------------------------
// Kernel 3: backtrack + emit fused. 128 blocks, one batch-chain per block.
// Ring deepened 8 -> 16 slots: prefetch distance ~16 steps (~560 cyc) vs
// L2 latency ~250-300 cyc; 48 outstanding LDG.
// ---------------------------------------------------------------------------
__device__ __forceinline__ int sel12(const uint4 (&r)[3], int tag) {
    unsigned q0 = r[0].x, q1 = r[0].y, q2 = r[0].z, q3 = r[0].w;
    unsigned q4 = r[1].x, q5 = r[1].y, q6 = r[1].z, q7 = r[1].w;
    unsigned q8 = r[2].x, q9 = r[2].y, q10 = r[2].z, q11 = r[2].w;
    int t2 = tag >> 2;
    unsigned w =
        t2 < 6 ? (t2 < 3 ? (t2 < 1 ? q0 : (t2 < 2 ? q1 : q2))
                         : (t2 < 4 ? q3 : (t2 < 5 ? q4 : q5)))
               : (t2 < 9 ? (t2 < 7 ? q6 : (t2 < 8 ? q7 : q8))
                         : (t2 < 10 ? q9 : (t2 < 11 ? q10 : q11)));
    return (int)((w >> ((tag & 3) << 3)) & 0xFFu);
}

__global__ __launch_bounds__(32) void backtrack_kernel(float* __restrict__ out) {
    const int b = blockIdx.x;
    if (threadIdx.x != 0) return;

    int tag = g_last[b];
    float* ob = out + (size_t)b * TT;
    ob[TT - 1] = (float)tag;

    uint4 ring[16][3];

    // prologue: steps 1022..1007 (slot = s & 15; 1022 & 15 = 14)
#pragma unroll
    for (int d = 0; d < 16; ++d) {
        int s = (TT - 2) - d;
        const uint4* r = (const uint4*)(g_bp + (size_t)s * BB * UU + (size_t)b * UU);
        ring[s & 15][0] = r[0];
        ring[s & 15][1] = r[1];
        ring[s & 15][2] = r[2];
    }

    // main: 63 groups of 16 -> steps 1022..15
    for (int g = 0; g < 63; ++g) {
        int sbase = (TT - 2) - g * 16;
#pragma unroll
        for (int d = 0; d < 16; ++d) {
            int s = sbase - d;
            const int slot = (14 - d) & 15;   // == s & 15, compile-time
            tag = sel12(ring[slot], tag);
            ob[s] = (float)tag;
            int sp = s - 16;
            if (sp >= 0) {
                const uint4* r = (const uint4*)(g_bp + (size_t)sp * BB * UU + (size_t)b * UU);
                ring[slot][0] = r[0];
                ring[slot][1] = r[1];
                ring[slot][2] = r[2];
            }
        }
    }

    // epilogue: steps 14..0 (already prefetched)
#pragma unroll
    for (int d = 0; d < 15; ++d) {
        int s = 14 - d;
        tag = sel12(ring[s & 15], tag);
        ob[s] = (float)tag;
    }
}

// ---------------------------------------------------------------------------
extern "C" void kernel_launch(void* const* d_in, const int* in_sizes, int n_in,
                              void* d_out, int out_size) {
    const float* x     = (const float*)d_in[0];  // (128,1024,256)
    const float* kern  = (const float*)d_in[1];  // (256,48)
    const float* bias  = (const float*)d_in[2];  // (48,)
    const float* chain = (const float*)d_in[3];  // (48,48)
    float* out = (float*)d_out;                  // (128,1024) float32

    gemm_kernel<<<(BB * TT) / GR, 128>>>(x, kern, bias);
    viterbi_fwd<<<BB, 96>>>(chain);
    backtrack_kernel<<<BB, 1>>>(out);
}

// round 5
// speedup vs baseline: 1.4643x; 1.0296x over previous
#include <cuda_runtime.h>
#include <stdint.h>

#define BB 128
#define TT 1024
#define DD 256
#define UU 48

// Scratch (allocation-free rule: __device__ globals)
__device__ float         g_logits[(size_t)BB * TT * UU];     // 25.2 MB
__device__ unsigned char g_bp[(size_t)(TT - 1) * BB * UU];   // 6.29 MB
__device__ int           g_last[BB];

#define ADD_F32X2(out, a, b) \
    asm("add.rn.f32x2 %0, %1, %2;" : "=l"(out) : "l"(a), "l"(b))

// ---------------------------------------------------------------------------
// Kernel 1: logits = x @ kernel + bias   (131072 x 48 x 256, fp32)
// Measured 105.5us ~= 1.12x the fp32 FFMA chip floor; unchanged.
// ---------------------------------------------------------------------------
#define GR 128
#define GK 64
#define XPAD 130

__global__ __launch_bounds__(128) void gemm_kernel(const float* __restrict__ x,
                                                   const float* __restrict__ w,
                                                   const float* __restrict__ bias) {
    __shared__ float xs[GK][XPAD];  // [k][row]
    __shared__ float ws[GK][UU];    // [k][col]

    const int tid = threadIdx.x;
    const int tc  = tid & 3;    // cols tc*12 .. +11
    const int tr  = tid >> 2;   // rows tr*4 .. +3
    const size_t row0 = (size_t)blockIdx.x * GR;

    float acc[4][12];
#pragma unroll
    for (int i = 0; i < 4; i++)
#pragma unroll
        for (int j = 0; j < 12; j++) acc[i][j] = 0.0f;

    for (int kc = 0; kc < DD; kc += GK) {
        const float4* wg = (const float4*)(w + (size_t)kc * UU);
        float4* wsv = (float4*)&ws[0][0];
#pragma unroll
        for (int i = 0; i < 6; i++) wsv[tid + i * 128] = wg[tid + i * 128];

#pragma unroll
        for (int i = 0; i < 16; i++) {
            int j  = tid + i * 128;
            int r  = j >> 4;
            int k4 = j & 15;
            float4 f = *(const float4*)(x + (row0 + (size_t)r) * DD + kc + k4 * 4);
            xs[k4 * 4 + 0][r] = f.x;
            xs[k4 * 4 + 1][r] = f.y;
            xs[k4 * 4 + 2][r] = f.z;
            xs[k4 * 4 + 3][r] = f.w;
        }
        __syncthreads();

#pragma unroll 4
        for (int k = 0; k < GK; k++) {
            float xv[4], wv[12];
            float2 xa = *(const float2*)&xs[k][tr * 4];
            float2 xb = *(const float2*)&xs[k][tr * 4 + 2];
            xv[0] = xa.x; xv[1] = xa.y; xv[2] = xb.x; xv[3] = xb.y;
#pragma unroll
            for (int q = 0; q < 3; q++) {
                float4 wq = *(const float4*)&ws[k][tc * 12 + q * 4];
                wv[q * 4 + 0] = wq.x; wv[q * 4 + 1] = wq.y;
                wv[q * 4 + 2] = wq.z; wv[q * 4 + 3] = wq.w;
            }
#pragma unroll
            for (int i = 0; i < 4; i++)
#pragma unroll
                for (int j = 0; j < 12; j++) acc[i][j] += xv[i] * wv[j];
        }
        __syncthreads();
    }

    float bv[12];
#pragma unroll
    for (int j = 0; j < 12; j++) bv[j] = bias[tc * 12 + j];

#pragma unroll
    for (int i = 0; i < 4; i++) {
        size_t r = row0 + tr * 4 + i;
        float* o = g_logits + r * UU + tc * 12;
#pragma unroll
        for (int j = 0; j < 12; j++) o[j] = acc[i][j] + bv[j];
    }
}

// ---------------------------------------------------------------------------
// Index-argmax over 24 candidates (half range), first-index tie-break
// (strict-greater replacement, left operand covers smaller indices).
// Used ONLY by index warps; never on the state recurrence chain.
// ---------------------------------------------------------------------------
__device__ __forceinline__ void argmax24(const unsigned long long (&c)[12],
                                         float& bvo, int& bio) {
    float v[12];
    int   ix[12];
#pragma unroll
    for (int j = 0; j < 12; j++) {
        float lo = __uint_as_float((unsigned)(c[j] & 0xFFFFFFFFull));
        float hi = __uint_as_float((unsigned)(c[j] >> 32));
        v[j]  = fmaxf(lo, hi);
        ix[j] = (hi > lo) ? (2 * j + 1) : (2 * j);
    }
#pragma unroll
    for (int j = 0; j < 6; j++) {
        float a = v[2 * j], b = v[2 * j + 1];
        v[j]  = fmaxf(a, b);
        ix[j] = (b > a) ? ix[2 * j + 1] : ix[2 * j];
    }
#pragma unroll
    for (int j = 0; j < 3; j++) {
        float a = v[2 * j], b = v[2 * j + 1];
        v[j]  = fmaxf(a, b);
        ix[j] = (b > a) ? ix[2 * j + 1] : ix[2 * j];
    }
    float m01 = fmaxf(v[0], v[1]);
    int  i01  = (v[1] > v[0]) ? ix[1] : ix[0];
    bvo = fmaxf(m01, v[2]);
    bio = (v[2] > m01) ? ix[2] : i01;
}

// ---------------------------------------------------------------------------
// Kernel 2: Viterbi forward, split warp groups. 160 threads per batch:
//   tid <  64 (2 warps): VALUE recurrence. Thread u (<48) computes
//     max_i(st[i] + trans[i][u]) via pure-fmaxf tree (no setp/sel/shfl on
//     chain), writes st[p^1][u]. Chain ~= LDS+add+tree+fadd+BAR.
//   tid >= 64 (3 warps): INDEX extraction. Thread (u = (tid-64)>>1,
//     h = (tid-64)&1) recomputes its 24 candidates from the SAME st[p] and
//     finds argmax (first-index ties), stores bp. Runs fully overlapped.
// ---------------------------------------------------------------------------
__global__ __launch_bounds__(160) void viterbi_fwd(const float* __restrict__ trans) {
    const int b   = blockIdx.x;
    const int tid = threadIdx.x;

    __shared__ __align__(16) float st[2][UU];

    const bool is_val = (tid < 64);
    const bool val_act = (tid < UU);

    // ---- value-thread setup ----
    const int uv = val_act ? tid : (UU - 1);
    unsigned long long trv[24];
    float f0, f1, f2, f3;
    const float* lg = g_logits + (size_t)b * TT * UU + uv;
    if (is_val) {
#pragma unroll
        for (int j = 0; j < 24; j++) {
            unsigned lo = __float_as_uint(trans[(2 * j) * UU + uv]);
            unsigned hi = __float_as_uint(trans[(2 * j + 1) * UU + uv]);
            trv[j] = (unsigned long long)lo | ((unsigned long long)hi << 32);
        }
        if (val_act) st[0][tid] = lg[0];
        f0 = lg[(size_t)1 * UU];
        f1 = lg[(size_t)2 * UU];
        f2 = lg[(size_t)3 * UU];
        f3 = lg[(size_t)4 * UU];
    }

    // ---- index-thread setup ----
    const int t2 = tid - 64;              // 0..95 when index thread
    const int ui = is_val ? 0 : (t2 >> 1);
    const int h  = is_val ? 0 : (t2 & 1);
    const int base = 24 * h;
    unsigned long long tri[12];
    if (!is_val) {
#pragma unroll
        for (int j = 0; j < 12; j++) {
            unsigned lo = __float_as_uint(trans[(base + 2 * j) * UU + ui]);
            unsigned hi = __float_as_uint(trans[(base + 2 * j + 1) * UU + ui]);
            tri[j] = (unsigned long long)lo | ((unsigned long long)hi << 32);
        }
    }
    unsigned char* bpb = g_bp + (size_t)b * UU + ui;

    __syncthreads();

    int p = 0;
    for (int t = 1; t < TT; ++t) {
        if (is_val) {
            float cur = f0;
            f0 = f1;
            f1 = f2;
            f2 = f3;
            int tn = t + 4;
            if (tn > TT - 1) tn = TT - 1;
            f3 = lg[(size_t)tn * UU];

            // 48 candidates: 12 LDS.128 + 24 packed adds
            unsigned long long c[24];
#pragma unroll
            for (int m = 0; m < 12; m++) {
                ulonglong2 s = *(const ulonglong2*)&st[p][4 * m];
                ADD_F32X2(c[2 * m + 0], s.x, trv[2 * m + 0]);
                ADD_F32X2(c[2 * m + 1], s.y, trv[2 * m + 1]);
            }
            // pure-fmaxf tree (value only)
            float v[24];
#pragma unroll
            for (int j = 0; j < 24; j++) {
                float lo = __uint_as_float((unsigned)(c[j] & 0xFFFFFFFFull));
                float hi = __uint_as_float((unsigned)(c[j] >> 32));
                v[j] = fmaxf(lo, hi);
            }
#pragma unroll
            for (int j = 0; j < 12; j++) v[j] = fmaxf(v[2 * j], v[2 * j + 1]);
#pragma unroll
            for (int j = 0; j < 6; j++)  v[j] = fmaxf(v[2 * j], v[2 * j + 1]);
#pragma unroll
            for (int j = 0; j < 3; j++)  v[j] = fmaxf(v[2 * j], v[2 * j + 1]);
            float bv = fmaxf(fmaxf(v[0], v[1]), v[2]);

            if (val_act) st[p ^ 1][tid] = cur + bv;
        } else {
            // index extraction for this same step, off the recurrence chain
            unsigned long long c[12];
#pragma unroll
            for (int m = 0; m < 6; m++) {
                ulonglong2 s = *(const ulonglong2*)&st[p][base + 4 * m];
                ADD_F32X2(c[2 * m + 0], s.x, tri[2 * m + 0]);
                ADD_F32X2(c[2 * m + 1], s.y, tri[2 * m + 1]);
            }
            float bv;
            int bi;
            argmax24(c, bv, bi);
            bi += base;

            float ov = __shfl_down_sync(0xFFFFFFFFu, bv, 1);
            int   oi = __shfl_down_sync(0xFFFFFFFFu, bi, 1);
            int   mi = (ov > bv) ? oi : bi;

            if (h == 0) bpb[(size_t)(t - 1) * BB * UU] = (unsigned char)mi;
        }
        __syncthreads();
        p ^= 1;
    }

    if (tid == 0) {
        float bv = st[p][0];
        int bi = 0;
#pragma unroll
        for (int i = 1; i < UU; i++) {
            if (st[p][i] > bv) { bv = st[p][i]; bi = i; }
        }
        g_last[b] = bi;
    }
}

// ---------------------------------------------------------------------------
// Kernel 3: backtrack + emit. 128 blocks (one batch each), 256 threads.
// Stage the batch's full bp column (1023 x 48 B = 48 KB) into SMEM in
// parallel, then walk the chain with a branchless LDS.U8 per step
// (chain ~= IADD + LDS = ~35 cyc/step). Output written as float directly.
// ---------------------------------------------------------------------------
__global__ __launch_bounds__(256) void backtrack_kernel(float* __restrict__ out) {
    __shared__ unsigned char sbp[(TT - 1) * UU];  // 49104 B (< 48 KB static limit)

    const int b = blockIdx.x;
    const int tid = threadIdx.x;

    // cooperative stage: 1023 rows x 3 uint4
    const unsigned char* gsrc = g_bp + (size_t)b * UU;
    for (int idx = tid; idx < (TT - 1) * 3; idx += 256) {
        int s = idx / 3;
        int w = idx % 3;
        uint4 v = *(const uint4*)(gsrc + (size_t)s * BB * UU + w * 16);
        *(uint4*)(sbp + s * UU + w * 16) = v;
    }
    __syncthreads();

    if (tid != 0) return;

    int tag = g_last[b];
    float* ob = out + (size_t)b * TT;
    ob[TT - 1] = (float)tag;

    int off = (TT - 2) * UU;
#pragma unroll 8
    for (int s = TT - 2; s >= 0; --s) {
        tag = sbp[off + tag];
        ob[s] = (float)tag;
        off -= UU;
    }
}

// ---------------------------------------------------------------------------
extern "C" void kernel_launch(void* const* d_in, const int* in_sizes, int n_in,
                              void* d_out, int out_size) {
    const float* x     = (const float*)d_in[0];  // (128,1024,256)
    const float* kern  = (const float*)d_in[1];  // (256,48)
    const float* bias  = (const float*)d_in[2];  // (48,)
    const float* chain = (const float*)d_in[3];  // (48,48)
    float* out = (float*)d_out;                  // (128,1024) float32

    gemm_kernel<<<(BB * TT) / GR, 128>>>(x, kern, bias);
    viterbi_fwd<<<BB, 160>>>(chain);
    backtrack_kernel<<<BB, 256>>>(out);
}